// round 1
// baseline (speedup 1.0000x reference)
#include <cuda_runtime.h>
#include <stdint.h>

#define NA 262144
#define NG 100

// ----------------- persistent scratch (device globals; no allocation) -----------------
__device__ float              g_max_ov[NA];
__device__ unsigned char      g_inside[NA];
__device__ unsigned char      g_cand[NA];
__device__ unsigned char      g_keptA[NA];   // cand after keep_at_most(R)
__device__ unsigned char      g_keptF[NA];   // fg kept
__device__ unsigned char      g_keptB[NA];   // bg kept
__device__ unsigned int       g_gtmax_enc[NG];
__device__ float              g_gtmax[NG];
__device__ float              g_min_gtmax;
__device__ int                g_nfg;
__device__ unsigned int       g_hist[4096];
__device__ int                g_state[2];    // [0]=boundary bin B (or 4096=keep all, -1=keep none), [1]=need within bin
__device__ unsigned long long g_buf[4096];
__device__ int                g_buf_cnt;

// ----------------- JAX threefry2x32 (partitionable path) -----------------
__host__ __device__ inline void tf2x32(unsigned k0, unsigned k1, unsigned x0, unsigned x1,
                                       unsigned &o0, unsigned &o1) {
    unsigned k2 = k0 ^ k1 ^ 0x1BD11BDAu;
    x0 += k0; x1 += k1;
#define RR(r) { x0 += x1; x1 = (x1 << (r)) | (x1 >> (32 - (r))); x1 ^= x0; }
    RR(13) RR(15) RR(26) RR(6)   x0 += k1; x1 += k2 + 1u;
    RR(17) RR(29) RR(16) RR(24)  x0 += k2; x1 += k0 + 2u;
    RR(13) RR(15) RR(26) RR(6)   x0 += k0; x1 += k1 + 3u;
    RR(17) RR(29) RR(16) RR(24)  x0 += k1; x1 += k2 + 4u;
    RR(13) RR(15) RR(26) RR(6)   x0 += k2; x1 += k0 + 5u;
#undef RR
    o0 = x0; o1 = x1;
}

// uniform(key,(N,)) element i: counts64=i -> (hi=0, lo=i); bits = o0^o1; float mantissa field:
__device__ __forceinline__ unsigned rng_v(unsigned ka, unsigned kb, unsigned i) {
    unsigned a, b; tf2x32(ka, kb, 0u, i, a, b);
    return (a ^ b) >> 9;   // 23-bit; uniform = v * 2^-23 (strictly monotone in v)
}

// ----------------- init -----------------
__global__ void k_init() {
    int t = threadIdx.x;
    for (int j = t; j < 4096; j += 1024) g_hist[j] = 0;
    if (t < NG) g_gtmax_enc[t] = 0x407FFFFFu;  // enc(-1.0f)
    if (t == 0) g_buf_cnt = 0;
}

// ----------------- pass 1: IoU, max_ov, gt_max -----------------
__global__ void __launch_bounds__(256) k_iou(const float4* __restrict__ anchors,
                                             const float* __restrict__ img,
                                             const float4* __restrict__ gt) {
    __shared__ float4  sg[NG];
    __shared__ float   sga[NG];
    __shared__ unsigned smax[NG];
    int t = threadIdx.x;
    if (t < NG) {
        float4 g = gt[t]; sg[t] = g;
        sga[t] = __fmul_rn(__fadd_rn(__fsub_rn(g.z, g.x), 1.0f),
                           __fadd_rn(__fsub_rn(g.w, g.y), 1.0f));
        smax[t] = 0x407FFFFFu;
    }
    __syncthreads();
    int i = blockIdx.x * 256 + t;
    float4 a = anchors[i];
    float H = img[0], W = img[1];
    bool inside = (a.x >= 0.0f) && (a.y >= 0.0f) && (a.z < W) && (a.w < H);
    float mo = -1.0f;
    if (inside) {
        float areaA = __fmul_rn(__fadd_rn(__fsub_rn(a.z, a.x), 1.0f),
                                __fadd_rn(__fsub_rn(a.w, a.y), 1.0f));
        #pragma unroll 4
        for (int r = 0; r < NG; r++) {
            float4 g = sg[r];
            float iw = __fadd_rn(__fsub_rn(fminf(a.z, g.z), fmaxf(a.x, g.x)), 1.0f);
            float ih = __fadd_rn(__fsub_rn(fminf(a.w, g.w), fmaxf(a.y, g.y)), 1.0f);
            float inter = __fmul_rn(fmaxf(iw, 0.0f), fmaxf(ih, 0.0f));
            float uni = __fsub_rn(__fadd_rn(areaA, sga[r]), inter);
            float q = __fdiv_rn(inter, uni);
            mo = fmaxf(mo, q);
            unsigned e = __float_as_uint(q) | 0x80000000u;   // q >= 0 always
            if (e > ((volatile unsigned*)smax)[r]) atomicMax(&smax[r], e);
        }
    }
    g_max_ov[i] = mo;
    g_inside[i] = inside ? 1 : 0;
    __syncthreads();
    if (t < NG) atomicMax(&g_gtmax_enc[t], smax[t]);
}

// ----------------- decode gt_max, compute min -----------------
__global__ void k_gtmax() {
    __shared__ float sm[128];
    int t = threadIdx.x;
    float v = 1e30f;
    if (t < NG) {
        unsigned e = g_gtmax_enc[t];
        v = (e & 0x80000000u) ? __uint_as_float(e & 0x7FFFFFFFu) : __uint_as_float(~e);
        g_gtmax[t] = v;
    }
    sm[t] = v; __syncthreads();
    for (int o = 64; o > 0; o >>= 1) { if (t < o) sm[t] = fminf(sm[t], sm[t + o]); __syncthreads(); }
    if (t == 0) g_min_gtmax = sm[0];
}

// ----------------- pass 2: candidate (per-gt argmax tie set) + hist for selection 1 -----------------
__global__ void __launch_bounds__(256) k_cand(const float4* __restrict__ anchors,
                                              const float4* __restrict__ gt,
                                              unsigned ka, unsigned kb) {
    __shared__ float4 sg[NG];
    __shared__ float  sga[NG];
    __shared__ float  sgm[NG];
    int t = threadIdx.x;
    if (t < NG) {
        float4 g = gt[t]; sg[t] = g;
        sga[t] = __fmul_rn(__fadd_rn(__fsub_rn(g.z, g.x), 1.0f),
                           __fadd_rn(__fsub_rn(g.w, g.y), 1.0f));
        sgm[t] = g_gtmax[t];
    }
    __syncthreads();
    int i = blockIdx.x * 256 + t;
    unsigned char c = 0;
    // prefilter: any r with q_r == gt_max[r] requires max_ov >= min_r gt_max[r]
    if (g_inside[i] && g_max_ov[i] >= g_min_gtmax) {
        float4 a = anchors[i];
        float areaA = __fmul_rn(__fadd_rn(__fsub_rn(a.z, a.x), 1.0f),
                                __fadd_rn(__fsub_rn(a.w, a.y), 1.0f));
        #pragma unroll 4
        for (int r = 0; r < NG; r++) {
            float4 g = sg[r];
            float iw = __fadd_rn(__fsub_rn(fminf(a.z, g.z), fmaxf(a.x, g.x)), 1.0f);
            float ih = __fadd_rn(__fsub_rn(fminf(a.w, g.w), fmaxf(a.y, g.y)), 1.0f);
            float inter = __fmul_rn(fmaxf(iw, 0.0f), fmaxf(ih, 0.0f));
            float uni = __fsub_rn(__fadd_rn(areaA, sga[r]), inter);
            float q = __fdiv_rn(inter, uni);
            if (q == sgm[r]) c = 1;
        }
    }
    g_cand[i] = c;
    if (c) { unsigned v = rng_v(ka, kb, (unsigned)i); atomicAdd(&g_hist[v >> 11], 1u); }
}

// ----------------- selection machinery -----------------
__device__ __forceinline__ bool sel_mask(int mode, int i) {
    if (mode == 0) return g_cand[i] != 0;
    if (mode == 1) return g_keptA[i] || (g_inside[i] && g_max_ov[i] >= 0.7f);
    return g_inside[i] && (g_max_ov[i] < 0.3f) && !g_keptA[i];
}

__global__ void __launch_bounds__(256) k_hist(int mode, unsigned ka, unsigned kb) {
    int i = blockIdx.x * 256 + threadIdx.x;
    if (sel_mask(mode, i)) {
        unsigned v = rng_v(ka, kb, (unsigned)i);
        atomicAdd(&g_hist[v >> 11], 1u);
    }
}

__global__ void __launch_bounds__(1024) k_thresh(int kfix, int sub_nfg, int wr_nfg) {
    __shared__ unsigned sc[1024];
    int t = threadIdx.x;
    unsigned h[4]; unsigned s = 0;
    #pragma unroll
    for (int j = 0; j < 4; j++) { h[j] = g_hist[4 * t + j]; s += h[j]; }
    sc[t] = s; __syncthreads();
    for (int o = 1; o < 1024; o <<= 1) {
        unsigned add = (t >= o) ? sc[t - o] : 0u;
        __syncthreads();
        sc[t] += add;
        __syncthreads();
    }
    unsigned total = sc[1023];
    unsigned excl = sc[t] - s;
    int k_eff = kfix - (sub_nfg ? g_nfg : 0);
    if (k_eff <= 0) {
        if (t == 0) { g_state[0] = -1; g_state[1] = 0; }
    } else if ((int)total <= k_eff) {
        if (t == 0) { g_state[0] = 4096; g_state[1] = 0; }
    } else {
        unsigned cum = excl;
        #pragma unroll
        for (int j = 0; j < 4; j++) {
            if ((int)cum < k_eff && (int)(cum + h[j]) >= k_eff) {
                g_state[0] = 4 * t + j;
                g_state[1] = k_eff - (int)cum;
            }
            cum += h[j];
        }
    }
    if (wr_nfg && t == 0) g_nfg = ((int)total < k_eff) ? (int)total : (k_eff < 0 ? 0 : k_eff);
    #pragma unroll
    for (int j = 0; j < 4; j++) g_hist[4 * t + j] = 0;
    if (t == 0) g_buf_cnt = 0;
}

__global__ void __launch_bounds__(256) k_mark(int mode, unsigned ka, unsigned kb) {
    int i = blockIdx.x * 256 + threadIdx.x;
    unsigned char* kept = (mode == 0) ? g_keptA : (mode == 1) ? g_keptF : g_keptB;
    unsigned char kv = 0;
    if (sel_mask(mode, i)) {
        unsigned v = rng_v(ka, kb, (unsigned)i);
        int bin = (int)(v >> 11);
        int B = g_state[0];
        if (bin < B) kv = 1;
        else if (bin == B) {
            int p = atomicAdd(&g_buf_cnt, 1);
            if (p < 4096) g_buf[p] = ((unsigned long long)v << 32) | (unsigned)i;
        }
    }
    kept[i] = kv;
}

__global__ void __launch_bounds__(1024) k_rank(int mode) {
    __shared__ unsigned long long sb[4096];
    unsigned char* kept = (mode == 0) ? g_keptA : (mode == 1) ? g_keptF : g_keptB;
    int n = g_buf_cnt; if (n > 4096) n = 4096;
    int need = g_state[1];
    int t = threadIdx.x;
    for (int e = t; e < n; e += 1024) sb[e] = g_buf[e];
    __syncthreads();
    for (int e = t; e < n; e += 1024) {
        unsigned long long k = sb[e];
        int rank = 0;
        for (int j = 0; j < n; j++) rank += (sb[j] < k);
        if (rank < need) kept[(unsigned)(k & 0xFFFFFFFFu)] = 1;
    }
}

// ----------------- final labels + bbox targets -----------------
__global__ void __launch_bounds__(256) k_final(const float4* __restrict__ anchors,
                                               const float4* __restrict__ gt,
                                               float* __restrict__ out) {
    __shared__ float4 sg[NG];
    int t = threadIdx.x;
    if (t < NG) sg[t] = gt[t];
    __syncthreads();
    int i = blockIdx.x * 256 + t;
    float mo = g_max_ov[i];
    bool inside = g_inside[i] != 0;
    float lab = -1.0f;
    if (inside) {
        if (mo < 0.3f) lab = 0.0f;
        if (g_keptA[i]) lab = 1.0f;
        if (mo >= 0.7f) lab = 1.0f;
        if (lab == 1.0f && !g_keptF[i]) lab = -1.0f;
        if (lab == 0.0f && !g_keptB[i]) lab = -1.0f;
    }
    out[i] = lab;

    int idx = __float2int_rz(mo);
    idx = max(0, min(idx, NG - 1));
    float4 g = sg[idx];
    float4 a = anchors[i];
    float o0 = 0.0f, o1 = 0.0f, o2 = 0.0f, o3 = 0.0f;
    if (inside) {
        float aw = a.z - a.x + 1.0f, ah = a.w - a.y + 1.0f;
        float acx = a.x + 0.5f * aw, acy = a.y + 0.5f * ah;
        float gw = g.z - g.x + 1.0f, gh = g.w - g.y + 1.0f;
        float gcx = g.x + 0.5f * gw, gcy = g.y + 0.5f * gh;
        o0 = (gcx - acx) / aw;
        o1 = (gcy - acy) / ah;
        o2 = logf(gw / aw);
        o3 = logf(gh / ah);
    }
    float* tp = out + NA + 4 * i;
    tp[0] = o0; tp[1] = o1; tp[2] = o2; tp[3] = o3;
}

// ----------------- launch -----------------
extern "C" void kernel_launch(void* const* d_in, const int* in_sizes, int n_in,
                              void* d_out, int out_size) {
    const float4* anchors = (const float4*)d_in[0];
    const float*  img     = (const float*)d_in[1];
    const float4* gt      = (const float4*)d_in[2];
    float* out = (float*)d_out;

    // jax.random.key(42) -> (0, 42); split(key, 3) via partitionable/foldlike path:
    // key_i = threefry2x32((0,42), (hi=0, lo=i))
    unsigned ks[3][2];
    for (unsigned i = 0; i < 3; i++) tf2x32(0u, 42u, 0u, i, ks[i][0], ks[i][1]);

    const int GB = NA / 256;
    k_init  <<<1, 1024>>>();
    k_iou   <<<GB, 256>>>(anchors, img, gt);
    k_gtmax <<<1, 128>>>();
    // selection 1: cand, k = R = 100, key k1
    k_cand  <<<GB, 256>>>(anchors, gt, ks[0][0], ks[0][1]);
    k_thresh<<<1, 1024>>>(NG, 0, 0);
    k_mark  <<<GB, 256>>>(0, ks[0][0], ks[0][1]);
    k_rank  <<<1, 1024>>>(0);
    // selection 2: fg, k = 128, key k2, writes n_fg
    k_hist  <<<GB, 256>>>(1, ks[1][0], ks[1][1]);
    k_thresh<<<1, 1024>>>(128, 0, 1);
    k_mark  <<<GB, 256>>>(1, ks[1][0], ks[1][1]);
    k_rank  <<<1, 1024>>>(1);
    // selection 3: bg, k = 256 - n_fg, key k3
    k_hist  <<<GB, 256>>>(2, ks[2][0], ks[2][1]);
    k_thresh<<<1, 1024>>>(256, 1, 0);
    k_mark  <<<GB, 256>>>(2, ks[2][0], ks[2][1]);
    k_rank  <<<1, 1024>>>(2);
    k_final <<<GB, 256>>>(anchors, gt, out);
}

// round 2
// speedup vs baseline: 1.2784x; 1.2784x over previous
#include <cuda_runtime.h>
#include <stdint.h>

#define NA 262144
#define NG 100

// ----------------- persistent scratch (device globals; no allocation) -----------------
__device__ float              g_max_ov[NA];
__device__ unsigned char      g_inside[NA];
__device__ unsigned char      g_cand[NA];
__device__ unsigned char      g_keptA[NA];   // cand after keep_at_most(R)
__device__ unsigned char      g_keptF[NA];   // fg kept
__device__ unsigned char      g_keptB[NA];   // bg kept
__device__ int                g_ilist[NA];   // compacted inside-anchor indices
__device__ int                g_icount;
__device__ int                g_clist[NA];   // compacted argmax-candidate indices
__device__ int                g_ccount;
__device__ unsigned int       g_gtmax_enc[NG];
__device__ int                g_nfg;
__device__ unsigned int       g_hist[4096];
__device__ int                g_state[2];    // [0]=boundary bin (4096=keep all, -1=none), [1]=need within bin
__device__ unsigned long long g_buf[4096];
__device__ int                g_buf_cnt;

// ----------------- JAX threefry2x32 (partitionable path) -----------------
__host__ __device__ inline void tf2x32(unsigned k0, unsigned k1, unsigned x0, unsigned x1,
                                       unsigned &o0, unsigned &o1) {
    unsigned k2 = k0 ^ k1 ^ 0x1BD11BDAu;
    x0 += k0; x1 += k1;
#define RR(r) { x0 += x1; x1 = (x1 << (r)) | (x1 >> (32 - (r))); x1 ^= x0; }
    RR(13) RR(15) RR(26) RR(6)   x0 += k1; x1 += k2 + 1u;
    RR(17) RR(29) RR(16) RR(24)  x0 += k2; x1 += k0 + 2u;
    RR(13) RR(15) RR(26) RR(6)   x0 += k0; x1 += k1 + 3u;
    RR(17) RR(29) RR(16) RR(24)  x0 += k1; x1 += k2 + 4u;
    RR(13) RR(15) RR(26) RR(6)   x0 += k2; x1 += k0 + 5u;
#undef RR
    o0 = x0; o1 = x1;
}

__device__ __forceinline__ unsigned rng_v(unsigned ka, unsigned kb, unsigned i) {
    unsigned a, b; tf2x32(ka, kb, 0u, i, a, b);
    return (a ^ b) >> 9;   // 23-bit mantissa field; uniform = v * 2^-23 (monotone)
}

__device__ __forceinline__ float dec_gtmax(unsigned e) {
    return (e & 0x80000000u) ? __uint_as_float(e & 0x7FFFFFFFu) : __uint_as_float(~e);
}

// ----------------- init -----------------
__global__ void k_init() {
    int t = threadIdx.x;
    for (int j = t; j < 4096; j += 1024) g_hist[j] = 0;
    if (t < NG) g_gtmax_enc[t] = 0x407FFFFFu;  // enc(-1.0f)
    if (t == 0) { g_buf_cnt = 0; g_icount = 0; g_ccount = 0; }
}

// ----------------- pass 0: inside mask + compaction -----------------
__global__ void __launch_bounds__(256) k_prep(const float4* __restrict__ anchors,
                                              const float* __restrict__ img) {
    int t = threadIdx.x;
    int i = blockIdx.x * 256 + t;
    float4 a = anchors[i];
    float H = img[0], W = img[1];
    bool inside = (a.x >= 0.0f) && (a.y >= 0.0f) && (a.z < W) && (a.w < H);
    g_inside[i] = inside ? 1 : 0;
    g_max_ov[i] = -1.0f;
    g_cand[i] = 0;
    unsigned m = __ballot_sync(0xFFFFFFFFu, inside);
    int lane = t & 31;
    int base = 0;
    if (lane == 0 && m) base = atomicAdd(&g_icount, __popc(m));
    base = __shfl_sync(0xFFFFFFFFu, base, 0);
    if (inside) g_ilist[base + __popc(m & ((1u << lane) - 1u))] = i;
}

// ----------------- pass 1: IoU over compacted inside list; max_ov + gt_max -----------------
__global__ void __launch_bounds__(256) k_iou(const float4* __restrict__ anchors,
                                             const float4* __restrict__ gt) {
    __shared__ float4   sg[NG];
    __shared__ float    sga[NG];
    __shared__ unsigned smax[NG];
    int t = threadIdx.x;
    if (t < NG) {
        float4 g = gt[t]; sg[t] = g;
        sga[t] = __fmul_rn(__fadd_rn(__fsub_rn(g.z, g.x), 1.0f),
                           __fadd_rn(__fsub_rn(g.w, g.y), 1.0f));
        smax[t] = 0x407FFFFFu;
    }
    __syncthreads();
    int n = g_icount;
    int idx = blockIdx.x * 256 + t;
    if (idx < n) {
        int i = g_ilist[idx];
        float4 a = anchors[i];
        float areaA = __fmul_rn(__fadd_rn(__fsub_rn(a.z, a.x), 1.0f),
                                __fadd_rn(__fsub_rn(a.w, a.y), 1.0f));
        float mo = -1.0f;
        #pragma unroll 4
        for (int r = 0; r < NG; r++) {
            float4 g = sg[r];
            float iw = __fadd_rn(__fsub_rn(fminf(a.z, g.z), fmaxf(a.x, g.x)), 1.0f);
            float ih = __fadd_rn(__fsub_rn(fminf(a.w, g.w), fmaxf(a.y, g.y)), 1.0f);
            float inter = __fmul_rn(fmaxf(iw, 0.0f), fmaxf(ih, 0.0f));
            float uni = __fsub_rn(__fadd_rn(areaA, sga[r]), inter);
            float q = __fdiv_rn(inter, uni);
            mo = fmaxf(mo, q);
            unsigned e = __float_as_uint(q) | 0x80000000u;   // q >= 0 always
            if (e > ((volatile unsigned*)smax)[r]) atomicMax(&smax[r], e);
        }
        g_max_ov[i] = mo;
    }
    __syncthreads();
    if (t < NG) atomicMax(&g_gtmax_enc[t], smax[t]);
}

// ----------------- pass 2a: compact candidate-superset (mo >= min gt_max) -----------------
__global__ void __launch_bounds__(256) k_candprep() {
    __shared__ float sm[128];
    int t = threadIdx.x;
    if (t < 128) sm[t] = (t < NG) ? dec_gtmax(g_gtmax_enc[t]) : 1e30f;
    __syncthreads();
    for (int o = 64; o > 0; o >>= 1) { if (t < o) sm[t] = fminf(sm[t], sm[t + o]); __syncthreads(); }
    float mn = sm[0];
    int i = blockIdx.x * 256 + t;
    bool c = (g_inside[i] != 0) && (g_max_ov[i] >= mn);
    unsigned m = __ballot_sync(0xFFFFFFFFu, c);
    int lane = t & 31;
    int base = 0;
    if (lane == 0 && m) base = atomicAdd(&g_ccount, __popc(m));
    base = __shfl_sync(0xFFFFFFFFu, base, 0);
    if (c) g_clist[base + __popc(m & ((1u << lane) - 1u))] = i;
}

// ----------------- pass 2b: exact tie-set over compacted candidates + hist(mode0) -----------------
__global__ void __launch_bounds__(256) k_cand(const float4* __restrict__ anchors,
                                              const float4* __restrict__ gt,
                                              unsigned ka, unsigned kb) {
    int n = g_ccount;
    if (blockIdx.x * 256 >= n) return;   // uniform per block
    __shared__ float4 sg[NG];
    __shared__ float  sga[NG];
    __shared__ float  sgm[NG];
    int t = threadIdx.x;
    if (t < NG) {
        float4 g = gt[t]; sg[t] = g;
        sga[t] = __fmul_rn(__fadd_rn(__fsub_rn(g.z, g.x), 1.0f),
                           __fadd_rn(__fsub_rn(g.w, g.y), 1.0f));
        sgm[t] = dec_gtmax(g_gtmax_enc[t]);
    }
    __syncthreads();
    int idx = blockIdx.x * 256 + t;
    if (idx >= n) return;
    int i = g_clist[idx];
    float4 a = anchors[i];
    float areaA = __fmul_rn(__fadd_rn(__fsub_rn(a.z, a.x), 1.0f),
                            __fadd_rn(__fsub_rn(a.w, a.y), 1.0f));
    bool c = false;
    #pragma unroll 4
    for (int r = 0; r < NG; r++) {
        float4 g = sg[r];
        float iw = __fadd_rn(__fsub_rn(fminf(a.z, g.z), fmaxf(a.x, g.x)), 1.0f);
        float ih = __fadd_rn(__fsub_rn(fminf(a.w, g.w), fmaxf(a.y, g.y)), 1.0f);
        float inter = __fmul_rn(fmaxf(iw, 0.0f), fmaxf(ih, 0.0f));
        float uni = __fsub_rn(__fadd_rn(areaA, sga[r]), inter);
        float q = __fdiv_rn(inter, uni);
        if (q == sgm[r]) c = true;
    }
    if (c) {
        g_cand[i] = 1;
        unsigned v = rng_v(ka, kb, (unsigned)i);
        atomicAdd(&g_hist[v >> 11], 1u);
    }
}

// ----------------- selection machinery -----------------
__device__ __forceinline__ bool sel_mask(int mode, int i) {
    if (mode == 0) return g_cand[i] != 0;
    if (mode == 1) return g_keptA[i] || (g_inside[i] && g_max_ov[i] >= 0.7f);
    return g_inside[i] && (g_max_ov[i] < 0.3f) && !g_keptA[i];
}

__global__ void __launch_bounds__(256) k_hist(int mode, unsigned ka, unsigned kb) {
    int i = blockIdx.x * 256 + threadIdx.x;
    if (sel_mask(mode, i)) {
        unsigned v = rng_v(ka, kb, (unsigned)i);
        atomicAdd(&g_hist[v >> 11], 1u);
    }
}

__global__ void __launch_bounds__(1024) k_thresh(int kfix, int sub_nfg, int wr_nfg) {
    __shared__ unsigned sc[1024];
    int t = threadIdx.x;
    unsigned h[4]; unsigned s = 0;
    #pragma unroll
    for (int j = 0; j < 4; j++) { h[j] = g_hist[4 * t + j]; s += h[j]; }
    sc[t] = s; __syncthreads();
    for (int o = 1; o < 1024; o <<= 1) {
        unsigned add = (t >= o) ? sc[t - o] : 0u;
        __syncthreads();
        sc[t] += add;
        __syncthreads();
    }
    unsigned total = sc[1023];
    unsigned excl = sc[t] - s;
    int k_eff = kfix - (sub_nfg ? g_nfg : 0);
    if (k_eff <= 0) {
        if (t == 0) { g_state[0] = -1; g_state[1] = 0; }
    } else if ((int)total <= k_eff) {
        if (t == 0) { g_state[0] = 4096; g_state[1] = 0; }
    } else {
        unsigned cum = excl;
        #pragma unroll
        for (int j = 0; j < 4; j++) {
            if ((int)cum < k_eff && (int)(cum + h[j]) >= k_eff) {
                g_state[0] = 4 * t + j;
                g_state[1] = k_eff - (int)cum;
            }
            cum += h[j];
        }
    }
    if (wr_nfg && t == 0) g_nfg = ((int)total < k_eff) ? (int)total : (k_eff < 0 ? 0 : k_eff);
    #pragma unroll
    for (int j = 0; j < 4; j++) g_hist[4 * t + j] = 0;
    if (t == 0) g_buf_cnt = 0;
}

__global__ void __launch_bounds__(256) k_mark(int mode, unsigned ka, unsigned kb) {
    int i = blockIdx.x * 256 + threadIdx.x;
    unsigned char* kept = (mode == 0) ? g_keptA : (mode == 1) ? g_keptF : g_keptB;
    unsigned char kv = 0;
    if (sel_mask(mode, i)) {
        unsigned v = rng_v(ka, kb, (unsigned)i);
        int bin = (int)(v >> 11);
        int B = g_state[0];
        if (bin < B) kv = 1;
        else if (bin == B) {
            int p = atomicAdd(&g_buf_cnt, 1);
            if (p < 4096) g_buf[p] = ((unsigned long long)v << 32) | (unsigned)i;
        }
    }
    kept[i] = kv;
}

__global__ void __launch_bounds__(1024) k_rank(int mode) {
    __shared__ unsigned long long sb[4096];
    unsigned char* kept = (mode == 0) ? g_keptA : (mode == 1) ? g_keptF : g_keptB;
    int n = g_buf_cnt; if (n > 4096) n = 4096;
    int need = g_state[1];
    int t = threadIdx.x;
    for (int e = t; e < n; e += 1024) sb[e] = g_buf[e];
    __syncthreads();
    for (int e = t; e < n; e += 1024) {
        unsigned long long k = sb[e];
        int rank = 0;
        for (int j = 0; j < n; j++) rank += (sb[j] < k);
        if (rank < need) kept[(unsigned)(k & 0xFFFFFFFFu)] = 1;
    }
}

// ----------------- final labels + bbox targets -----------------
__global__ void __launch_bounds__(256) k_final(const float4* __restrict__ anchors,
                                               const float4* __restrict__ gt,
                                               float* __restrict__ out) {
    __shared__ float4 sg[NG];
    int t = threadIdx.x;
    if (t < NG) sg[t] = gt[t];
    __syncthreads();
    int i = blockIdx.x * 256 + t;
    float mo = g_max_ov[i];
    bool inside = g_inside[i] != 0;
    float lab = -1.0f;
    if (inside) {
        if (mo < 0.3f) lab = 0.0f;
        if (g_keptA[i]) lab = 1.0f;
        if (mo >= 0.7f) lab = 1.0f;
        if (lab == 1.0f && !g_keptF[i]) lab = -1.0f;
        if (lab == 0.0f && !g_keptB[i]) lab = -1.0f;
    }
    out[i] = lab;

    int idx = __float2int_rz(mo);
    idx = max(0, min(idx, NG - 1));
    float4 g = sg[idx];
    float4 a = anchors[i];
    float o0 = 0.0f, o1 = 0.0f, o2 = 0.0f, o3 = 0.0f;
    if (inside) {
        float aw = a.z - a.x + 1.0f, ah = a.w - a.y + 1.0f;
        float acx = a.x + 0.5f * aw, acy = a.y + 0.5f * ah;
        float gw = g.z - g.x + 1.0f, gh = g.w - g.y + 1.0f;
        float gcx = g.x + 0.5f * gw, gcy = g.y + 0.5f * gh;
        o0 = (gcx - acx) / aw;
        o1 = (gcy - acy) / ah;
        o2 = logf(gw / aw);
        o3 = logf(gh / ah);
    }
    float* tp = out + NA + 4 * i;
    tp[0] = o0; tp[1] = o1; tp[2] = o2; tp[3] = o3;
}

// ----------------- launch -----------------
extern "C" void kernel_launch(void* const* d_in, const int* in_sizes, int n_in,
                              void* d_out, int out_size) {
    const float4* anchors = (const float4*)d_in[0];
    const float*  img     = (const float*)d_in[1];
    const float4* gt      = (const float4*)d_in[2];
    float* out = (float*)d_out;

    // jax.random.key(42) -> (0,42); split via partitionable/foldlike path:
    // key_i = threefry2x32((0,42), (hi=0, lo=i))
    unsigned ks[3][2];
    for (unsigned i = 0; i < 3; i++) tf2x32(0u, 42u, 0u, i, ks[i][0], ks[i][1]);

    const int GB = NA / 256;
    k_init    <<<1, 1024>>>();
    k_prep    <<<GB, 256>>>(anchors, img);
    k_iou     <<<GB, 256>>>(anchors, gt);
    k_candprep<<<GB, 256>>>();
    k_cand    <<<GB, 256>>>(anchors, gt, ks[0][0], ks[0][1]);
    // selection 1: cand, k = R = 100, key k1 (hist already accumulated in k_cand)
    k_thresh  <<<1, 1024>>>(NG, 0, 0);
    k_mark    <<<GB, 256>>>(0, ks[0][0], ks[0][1]);
    k_rank    <<<1, 1024>>>(0);
    // selection 2: fg, k = 128, key k2, writes n_fg
    k_hist    <<<GB, 256>>>(1, ks[1][0], ks[1][1]);
    k_thresh  <<<1, 1024>>>(128, 0, 1);
    k_mark    <<<GB, 256>>>(1, ks[1][0], ks[1][1]);
    k_rank    <<<1, 1024>>>(1);
    // selection 3: bg, k = 256 - n_fg, key k3
    k_hist    <<<GB, 256>>>(2, ks[2][0], ks[2][1]);
    k_thresh  <<<1, 1024>>>(256, 1, 0);
    k_mark    <<<GB, 256>>>(2, ks[2][0], ks[2][1]);
    k_rank    <<<1, 1024>>>(2);
    k_final   <<<GB, 256>>>(anchors, gt, out);
}